// round 7
// baseline (speedup 1.0000x reference)
#include <cuda_runtime.h>
#include <cuda_bf16.h>

// Problem geometry: [B=4, 1, D=160, H=160, W=160]
#define NB 4
#define S  160
#define PLANE4      6400           // float4/int4 per (b,d) plane
#define PLANE_ELEMS 25600
#define CHUNK4      800            // 20 rows x 40 quads
#define MAIN_CHUNKS 5120           // pred/true SS chunks
#define DWIN_ITEMS  256            // 4 batches x 8 window planes x 8 parts
#define HWIN_ITEMS  640            // one per (b,d) plane
#define WWIN_ITEMS  640            // one per (b,d) plane
#define TOTAL_ITEMS (MAIN_CHUNKS + DWIN_ITEMS + HWIN_ITEMS + WWIN_ITEMS)  // 6656
#define NBLOCKS_A   (148 * 12)     // 1776
#define NTHREADS_A  160
#define NBLOCKS_B   148            // <= 1/SM: always co-resident (safe spin)
#define NTHREADS_B  256
#define TOTAL_ELEMS (4.0 * 160.0 * 160.0 * 160.0)

// ---- device scratch (zero at load; kB's last block re-zeroes everything) ----
__device__ unsigned char g_winD[NB][8];   // window any-flags (0..3 = low, 4..7 = high)
__device__ unsigned char g_winH[NB][8];
__device__ unsigned char g_winW[NB][8];
__device__ unsigned char g_any[NB][3][S]; // full projections (fallback path only)
__device__ int      g_lo[NB][3];
__device__ int      g_hi[NB][3];
__device__ int      g_fallback;
__device__ int      g_ready;
__device__ double   g_ss_all;
__device__ double   g_ss_out;
__device__ unsigned g_done_A, g_done_pB, g_done_B;

// Exact f32 replication of the reference bbox math (mn<0 -> empty box).
__device__ __forceinline__ void bbox_from(int mn, int mx, int* lo, int* hi) {
    if (mn < 0) { *lo = 0; *hi = 0; return; }
    float c = ((float)mx + (float)mn) * 0.5f;
    float e = ((float)mx - (float)mn + 1.0f) * 0.5f * 1.2f;   // EXPAND
    *lo = (int)fmaxf(0.0f, floorf(c - e));
    *hi = (int)fminf((float)(S - 1), floorf(c + e));          // EXCLUSIVE
}

// ===================== kernel A: SS_all stream + mask boundary windows ======
// Grid-stride over 6656 items: 5120 unweighted-SS chunks (131MB, no bbox
// dependency) + 1536 mask window items (~13MB). Last-done block derives the
// bbox from the window flags, or flags fallback if any axis end is unresolved.
__global__ __launch_bounds__(NTHREADS_A, 12) void kA(const float* __restrict__ pred,
                                                     const float* __restrict__ truth,
                                                     const int*   __restrict__ mask) {
    __shared__ double warpSum[5];
    __shared__ int sLast;

    const int tid = threadIdx.x;
    const int rg  = tid / 40;            // 0..3
    const int c   = tid % 40;

    float acc = 0.0f;
    for (int item = blockIdx.x; item < TOTAL_ITEMS; item += NBLOCKS_A) {
        if (item < MAIN_CHUNKS) {
            // ---- unweighted SS chunk: 20 rows x 40 float4, both arrays ----
            const int base = (item >> 3) * PLANE4 + (item & 7) * CHUNK4 + tid;
            const float4* P = (const float4*)pred  + base;
            const float4* T = (const float4*)truth + base;
            #pragma unroll
            for (int k = 0; k < 5; k++) {
                float4 p = P[160 * k];
                float4 t = T[160 * k];
                float dx = p.x - t.x, dy = p.y - t.y, dz = p.z - t.z, dw = p.w - t.w;
                acc = fmaf(dx, dx, acc);
                acc = fmaf(dy, dy, acc);
                acc = fmaf(dz, dz, acc);
                acc = fmaf(dw, dw, acc);
            }
        } else if (item < MAIN_CHUNKS + DWIN_ITEMS) {
            // ---- D window: any over chunk of plane d in {0..3,156..159} ----
            int i    = item - MAIN_CHUNKS;
            int b    = i >> 6;
            int wp   = (i >> 3) & 7;
            int part = i & 7;
            int d    = (wp < 4) ? wp : 152 + wp;
            const int4* M = (const int4*)mask + (b * S + d) * PLANE4 + part * CHUNK4 + tid;
            int o = 0;
            #pragma unroll
            for (int k = 0; k < 5; k++) {
                int4 v = M[160 * k];
                o |= v.x | v.y | v.z | v.w;
            }
            if (__syncthreads_or(o)) { if (tid == 0) g_winD[b][wp] = 1; }
        } else if (item < MAIN_CHUNKS + DWIN_ITEMS + HWIN_ITEMS) {
            // ---- H window: rows {0..3,156..159} of one plane ----
            int p = item - (MAIN_CHUNKS + DWIN_ITEMS);    // 0..639
            int b = p / S;
            const int4* M = (const int4*)mask + p * PLANE4;
            int4 va = M[tid];                              // row rg (= tid/40)
            int4 vb = M[6240 + tid];                       // row 156+rg
            if (va.x | va.y | va.z | va.w) g_winH[b][rg]     = 1;
            if (vb.x | vb.y | vb.z | vb.w) g_winH[b][4 + rg] = 1;
        } else {
            // ---- W window: first/last int4 of every row of one plane ----
            int p = item - (MAIN_CHUNKS + DWIN_ITEMS + HWIN_ITEMS);
            int b = p / S;
            const int4* M = (const int4*)mask + p * PLANE4 + tid * 40;
            int4 v0 = M[0];                                // w 0..3
            int4 v1 = M[39];                               // w 156..159
            unsigned r0 = __reduce_or_sync(0xFFFFFFFFu, (unsigned)v0.x);
            unsigned r1 = __reduce_or_sync(0xFFFFFFFFu, (unsigned)v0.y);
            unsigned r2 = __reduce_or_sync(0xFFFFFFFFu, (unsigned)v0.z);
            unsigned r3 = __reduce_or_sync(0xFFFFFFFFu, (unsigned)v0.w);
            unsigned r4 = __reduce_or_sync(0xFFFFFFFFu, (unsigned)v1.x);
            unsigned r5 = __reduce_or_sync(0xFFFFFFFFu, (unsigned)v1.y);
            unsigned r6 = __reduce_or_sync(0xFFFFFFFFu, (unsigned)v1.z);
            unsigned r7 = __reduce_or_sync(0xFFFFFFFFu, (unsigned)v1.w);
            if ((tid & 31) == 0) {
                if (r0) g_winW[b][0] = 1;
                if (r1) g_winW[b][1] = 1;
                if (r2) g_winW[b][2] = 1;
                if (r3) g_winW[b][3] = 1;
                if (r4) g_winW[b][4] = 1;
                if (r5) g_winW[b][5] = 1;
                if (r6) g_winW[b][6] = 1;
                if (r7) g_winW[b][7] = 1;
            }
        }
    }

    // block reduce SS -> one double atomic per block
    #pragma unroll
    for (int off = 16; off > 0; off >>= 1)
        acc += __shfl_xor_sync(0xFFFFFFFFu, acc, off);
    if ((tid & 31) == 0) warpSum[tid >> 5] = (double)acc;
    __syncthreads();
    if (tid == 0) {
        double s = 0.0;
        #pragma unroll
        for (int w = 0; w < 5; w++) s += warpSum[w];
        atomicAdd(&g_ss_all, s);
    }

    // last-done block: bbox from window flags (or fallback)
    __threadfence();
    if (tid == 0) sLast = (atomicAdd(&g_done_A, 1u) == (unsigned)(NBLOCKS_A - 1));
    __syncthreads();
    if (sLast && tid == 0) {
        int fb = 0;
        for (int b = 0; b < NB; b++) {
            volatile unsigned char* wA[3] = { g_winD[b], g_winH[b], g_winW[b] };
            int mn[3], mx[3], ok = 1;
            for (int ax = 0; ax < 3; ax++) {
                int m0 = -1, m1 = -1;
                for (int k = 0; k < 4; k++)  if (wA[ax][k] && m0 < 0) m0 = k;
                for (int k = 7; k >= 4; k--) if (wA[ax][k] && m1 < 0) m1 = 152 + k;
                mn[ax] = m0; mx[ax] = m1;
                if (m0 < 0 || m1 < 0) ok = 0;      // end unresolved -> fallback
            }
            if (ok) {
                for (int ax = 0; ax < 3; ax++) {
                    int lo, hi;
                    bbox_from(mn[ax], mx[ax], &lo, &hi);
                    g_lo[b][ax] = lo; g_hi[b][ax] = hi;
                }
            } else {
                fb = 1;
            }
        }
        g_fallback = fb;
        __threadfence();
        if (!fb) *(volatile int*)&g_ready = 1;
    }
}

// ===================== kernel B: (rare) fallback + SS_out + finalize ========
// 148 blocks (always co-resident => internal spin is safe). Common path skips
// straight to SS_out over the box complement (~2% of voxels).
__global__ __launch_bounds__(NTHREADS_B) void kB(const float* __restrict__ pred,
                                                 const float* __restrict__ truth,
                                                 const int*   __restrict__ mask,
                                                 float* __restrict__ out) {
    __shared__ double warpSum[8];
    __shared__ int sLast;
    const int tid = threadIdx.x;

    if (g_fallback) {
        // full mask projection (threads 0..159 active; rare path)
        const int rg = tid / 40, c = tid % 40;
        for (int chunk = blockIdx.x; chunk < MAIN_CHUNKS; chunk += NBLOCKS_B) {
            if (tid < 160) {
                int plane = chunk >> 3, part = chunk & 7;
                int b = plane / S, d = plane - b * S;
                const int4* M = (const int4*)mask + plane * PLANE4 + part * CHUNK4 + tid;
                int4 o = make_int4(0, 0, 0, 0);
                #pragma unroll
                for (int k = 0; k < 5; k++) {
                    int4 v = M[160 * k];
                    o.x |= v.x; o.y |= v.y; o.z |= v.z; o.w |= v.w;
                    if (v.x | v.y | v.z | v.w) {
                        g_any[b][1][part * 20 + rg + 4 * k] = 1;
                        g_any[b][0][d] = 1;
                    }
                }
                if (o.x) g_any[b][2][c * 4 + 0] = 1;
                if (o.y) g_any[b][2][c * 4 + 1] = 1;
                if (o.z) g_any[b][2][c * 4 + 2] = 1;
                if (o.w) g_any[b][2][c * 4 + 3] = 1;
            }
        }
        __threadfence();
        if (tid == 0) {
            if (atomicAdd(&g_done_pB, 1u) == (unsigned)(NBLOCKS_B - 1)) {
                for (int b = 0; b < NB; b++)
                    for (int ax = 0; ax < 3; ax++) {
                        volatile unsigned char* a = &g_any[b][ax][0];
                        int mn = -1, mx = -1;
                        for (int i = 0; i < S; i++)
                            if (a[i]) { if (mn < 0) mn = i; mx = i; }
                        int lo, hi;
                        bbox_from(mn, mx, &lo, &hi);
                        g_lo[b][ax] = lo; g_hi[b][ax] = hi;
                    }
                __threadfence();
                *(volatile int*)&g_ready = 1;
            }
            while (!*(volatile int*)&g_ready) { }
        }
        __syncthreads();
    }

    // ---- SS_out over the complement of the box ----
    float acc = 0.0f;
    for (int p = blockIdx.x; p < NB * S; p += NBLOCKS_B) {
        int b = p / S, d = p - b * S;
        int loD = g_lo[b][0], hiD = g_hi[b][0];
        int loH = g_lo[b][1], hiH = g_hi[b][1];
        int loW = g_lo[b][2], hiW = g_hi[b][2];
        const float* Pp = pred  + (size_t)p * PLANE_ELEMS;
        const float* Tp = truth + (size_t)p * PLANE_ELEMS;

        if (d < loD || d >= hiD) {
            // whole plane is outside
            const float4* P4 = (const float4*)Pp;
            const float4* T4 = (const float4*)Tp;
            for (int i = tid; i < PLANE4; i += NTHREADS_B) {
                float4 pv = P4[i], tv = T4[i];
                float dx = pv.x - tv.x, dy = pv.y - tv.y, dz = pv.z - tv.z, dw = pv.w - tv.w;
                acc = fmaf(dx, dx, acc);
                acc = fmaf(dy, dy, acc);
                acc = fmaf(dz, dz, acc);
                acc = fmaf(dw, dw, acc);
            }
        } else {
            // rows fully outside the H range
            int nOutH = loH + (S - hiH);
            const float4* P4 = (const float4*)Pp;
            const float4* T4 = (const float4*)Tp;
            for (int j = tid; j < nOutH * 40; j += NTHREADS_B) {
                int k = j / 40, cc = j - k * 40;
                int h = (k < loH) ? k : hiH + (k - loH);
                int idx = h * 40 + cc;
                float4 pv = P4[idx], tv = T4[idx];
                float dx = pv.x - tv.x, dy = pv.y - tv.y, dz = pv.z - tv.z, dw = pv.w - tv.w;
                acc = fmaf(dx, dx, acc);
                acc = fmaf(dy, dy, acc);
                acc = fmaf(dz, dz, acc);
                acc = fmaf(dw, dw, acc);
            }
            // W stubs of inside rows
            int nStub = loW + (S - hiW);
            int nInH  = hiH - loH;
            for (int j = tid; j < nInH * nStub; j += NTHREADS_B) {
                int r = j / nStub, s = j - r * nStub;
                int h = loH + r;
                int w = (s < loW) ? s : hiW + (s - loW);
                float dv = Pp[h * S + w] - Tp[h * S + w];
                acc = fmaf(dv, dv, acc);
            }
        }
    }

    #pragma unroll
    for (int off = 16; off > 0; off >>= 1)
        acc += __shfl_xor_sync(0xFFFFFFFFu, acc, off);
    if ((tid & 31) == 0) warpSum[tid >> 5] = (double)acc;
    __syncthreads();
    if (tid == 0) {
        double s = 0.0;
        #pragma unroll
        for (int w = 0; w < 8; w++) s += warpSum[w];
        atomicAdd(&g_ss_out, s);
    }

    // last block: finalize + reset ALL scratch for the next graph replay
    __threadfence();
    if (tid == 0) sLast = (atomicAdd(&g_done_B, 1u) == (unsigned)(NBLOCKS_B - 1));
    __syncthreads();
    if (sLast) {
        if (tid == 0) {
            double sa = atomicAdd(&g_ss_all, 0.0);
            double so = atomicAdd(&g_ss_out, 0.0);
            out[0] = (float)((sa - 0.99 * so) / TOTAL_ELEMS);
            g_ss_all = 0.0; g_ss_out = 0.0;
            g_done_A = 0u; g_done_pB = 0u; g_done_B = 0u;
            g_fallback = 0;
            *(volatile int*)&g_ready = 0;
        }
        if (tid < 32) {
            ((unsigned char*)g_winD)[tid] = 0;
            ((unsigned char*)g_winH)[tid] = 0;
            ((unsigned char*)g_winW)[tid] = 0;
        }
        int* pz = (int*)g_any;                    // 1920 bytes = 480 ints
        for (int i = tid; i < (NB * 3 * S) / 4; i += NTHREADS_B) pz[i] = 0;
    }
}

extern "C" void kernel_launch(void* const* d_in, const int* in_sizes, int n_in,
                              void* d_out, int out_size) {
    const float* y_pred = (const float*)d_in[0];
    const float* y_true = (const float*)d_in[1];
    const int*   mask   = (const int*)d_in[2];
    float* out = (float*)d_out;

    kA<<<NBLOCKS_A, NTHREADS_A>>>(y_pred, y_true, mask);
    kB<<<NBLOCKS_B, NTHREADS_B>>>(y_pred, y_true, mask, out);
}